// round 10
// baseline (speedup 1.0000x reference)
#include <cuda_runtime.h>
#include <math.h>
#include <stdint.h>

// ---------------------------------------------------------------------------
// AMNet: GCN-normalized Bernstein-filter GNN.
// Identities used:
//   B0 = 0.25(h + 2p + q), B1 = 0.5(h - q), B2 = 0.25(h - 2p + q)
//     with p = A_hat h, q = A_hat p
//   (A_hat X) @ Wf = A_hat (X @ Wf)  -> PF = A_hat HF, QF = A_hat PF
// so only ONE projection GEMM (HF = h@Wf) is needed; PF/QF come from props.
#define NN   100000
#define EE   1600000
#define INF  166
#define HID  156
#define LD   160
#define FN   4
#define NB_SCAN 196
#define DET_N 65536

#define S_H  0
#define S_HF 1
#define S_P  2
#define S_PF 3
#define S_Q  4
#define S_QF 5
#define S_XP 6
#define S_T  7

__device__ float g_buf[(size_t)8 * NN * LD];
__device__ float g_hb[FN * LD];
__device__ float g_dinv[NN];
__device__ int   g_deg[NN];
__device__ int   g_cur[NN];
__device__ int   g_rowptr[NN + 1];
__device__ int   g_csrc[EE];
__device__ float g_cw[EE];
__device__ int   g_bsum[NB_SCAN];
__device__ int   g_odd_or;   // 0 => edge_index int64; nonzero => int32

__device__ __forceinline__ float* BUF(int i)
{
    return g_buf + (size_t)i * (NN * LD);
}

__device__ __forceinline__ int clampN(int v)
{
    return ((unsigned)v >= (unsigned)NN) ? 0 : v;
}

__device__ __forceinline__ int edge_at(const void* ei, long long j)
{
    if (g_odd_or == 0) return clampN((int)((const long long*)ei)[j]);
    return clampN(((const int*)ei)[j]);
}

// ---------------------------- CSR construction -----------------------------
__global__ void k_zero()
{
    int i = blockIdx.x * blockDim.x + threadIdx.x;
    if (i == 0) g_odd_or = 0;
    if (i < NN) { g_deg[i] = 0; g_cur[i] = 0; }
}

__global__ void k_det(const int* __restrict__ w)
{
    int i = blockIdx.x * blockDim.x + threadIdx.x;
    if (i < DET_N) {
        if (w[2 * i + 1] != 0) atomicOr(&g_odd_or, 1);
    }
}

__global__ void k_count(const void* ei)
{
    int e = blockIdx.x * blockDim.x + threadIdx.x;
    if (e < EE) atomicAdd(&g_deg[edge_at(ei, (long long)EE + e)], 1);
}

__global__ void k_scan1()
{
    __shared__ int s[512];
    int tid = threadIdx.x;
    int i = blockIdx.x * 512 + tid;
    int v = (i < NN) ? g_deg[i] : 0;
    if (i < NN) g_dinv[i] = rsqrtf(fmaxf((float)v, 1.0f));
    s[tid] = v;
    __syncthreads();
    for (int off = 1; off < 512; off <<= 1) {
        int t = (tid >= off) ? s[tid - off] : 0;
        __syncthreads();
        s[tid] += t;
        __syncthreads();
    }
    if (i < NN) g_rowptr[i] = s[tid] - v;
    if (tid == 511) g_bsum[blockIdx.x] = s[511];
}

__global__ void k_scan2()
{
    int acc = 0;
    for (int i = 0; i < NB_SCAN; i++) {
        int t = g_bsum[i];
        g_bsum[i] = acc;
        acc += t;
    }
    g_rowptr[NN] = EE;
}

__global__ void k_scan3()
{
    int i = blockIdx.x * 512 + threadIdx.x;
    if (i < NN) g_rowptr[i] += g_bsum[blockIdx.x];
}

__global__ void k_fill(const void* ei)
{
    int e = blockIdx.x * blockDim.x + threadIdx.x;
    if (e < EE) {
        int s = edge_at(ei, e);
        int d = edge_at(ei, (long long)EE + e);
        int pos = atomicAdd(&g_cur[d], 1);
        int idx = g_rowptr[d] + pos;
        g_csrc[idx] = s;
        g_cw[idx]   = g_dinv[s] * g_dinv[d];
    }
}

// ------------------------- tf32 tensor-core GEMM ---------------------------
__device__ __forceinline__ uint32_t f2tf32(float f)
{
    uint32_t r;
    asm("cvt.rna.tf32.f32 %0, %1;" : "=r"(r) : "f"(f));
    return r;
}

__device__ __forceinline__ void mma8(float* c, const uint32_t* a,
                                     uint32_t b0, uint32_t b1)
{
    asm volatile(
        "mma.sync.aligned.m16n8k8.row.col.f32.tf32.tf32.f32 "
        "{%0,%1,%2,%3}, {%4,%5,%6,%7}, {%8,%9}, {%0,%1,%2,%3};"
        : "+f"(c[0]), "+f"(c[1]), "+f"(c[2]), "+f"(c[3])
        : "r"(a[0]), "r"(a[1]), "r"(a[2]), "r"(a[3]), "r"(b0), "r"(b1));
}

// C[M x Nc] = act(A @ W + bias). Block tile 128x160, BK=32, reg-prefetch.
__global__ __launch_bounds__(256)
void k_gemm_tf32(const float* __restrict__ Aext, int Asel, int lda,
                 const float* __restrict__ W,
                 const float* __restrict__ bias,
                 int Csel, int M, int Kc, int Nc, int act)
{
    __shared__ uint32_t As[128][36];
    __shared__ uint32_t Bs[32][168];

    const float* A = (Asel >= 0) ? BUF(Asel) : Aext;
    float*       C = BUF(Csel);

    int t = threadIdx.x;
    int lane = t & 31, warp = t >> 5;
    int wm = warp & 3, wn = warp >> 2;
    int g = lane >> 2, tg = lane & 3;
    int rowbase = blockIdx.x * 128;

    int ar  = t >> 1;
    int ac0 = (t & 1) * 16;
    int gr  = rowbase + ar;
    bool rok = gr < M;
    const float* Arow = A + (size_t)gr * lda + ac0;

    float ra[16], rb[20];

    #pragma unroll
    for (int i = 0; i < 16; i++) {
        int gk = ac0 + i;
        ra[i] = (rok && gk < Kc) ? Arow[i] : 0.0f;
    }
    #pragma unroll
    for (int i = 0; i < 20; i++) {
        int idx = t + i * 256;
        int r = idx / 160, c = idx - r * 160;
        rb[i] = (r < Kc && c < Nc) ? W[r * Nc + c] : 0.0f;
    }

    float acc[2][10][4];
    #pragma unroll
    for (int mt = 0; mt < 2; mt++)
        #pragma unroll
        for (int nt = 0; nt < 10; nt++)
            #pragma unroll
            for (int q = 0; q < 4; q++) acc[mt][nt][q] = 0.0f;

    for (int k0 = 0; k0 < Kc; k0 += 32) {
        #pragma unroll
        for (int i = 0; i < 16; i++)
            As[ar][ac0 + i] = f2tf32(ra[i]);
        #pragma unroll
        for (int i = 0; i < 20; i++) {
            int idx = t + i * 256;
            int r = idx / 160, c = idx - r * 160;
            Bs[r][c] = f2tf32(rb[i]);
        }
        __syncthreads();

        int kn = k0 + 32;
        if (kn < Kc) {
            const float* An = Arow + kn;
            #pragma unroll
            for (int i = 0; i < 16; i++) {
                int gk = kn + ac0 + i;
                ra[i] = (rok && gk < Kc) ? An[i] : 0.0f;
            }
            #pragma unroll
            for (int i = 0; i < 20; i++) {
                int idx = t + i * 256;
                int r = idx / 160, c = idx - r * 160;
                int gk = kn + r;
                rb[i] = (gk < Kc && c < Nc) ? W[gk * Nc + c] : 0.0f;
            }
        }

        #pragma unroll
        for (int kk = 0; kk < 32; kk += 8) {
            uint32_t a[2][4];
            #pragma unroll
            for (int mt = 0; mt < 2; mt++) {
                int mr = wm * 32 + mt * 16 + g;
                a[mt][0] = As[mr][kk + tg];
                a[mt][1] = As[mr + 8][kk + tg];
                a[mt][2] = As[mr][kk + tg + 4];
                a[mt][3] = As[mr + 8][kk + tg + 4];
            }
            #pragma unroll
            for (int nt = 0; nt < 10; nt++) {
                int nb = wn * 80 + nt * 8 + g;
                uint32_t b0 = Bs[kk + tg][nb];
                uint32_t b1 = Bs[kk + tg + 4][nb];
                mma8(acc[0][nt], a[0], b0, b1);
                mma8(acc[1][nt], a[1], b0, b1);
            }
        }
        __syncthreads();
    }

    #pragma unroll
    for (int mt = 0; mt < 2; mt++) {
        int r0 = rowbase + wm * 32 + mt * 16 + g;
        #pragma unroll
        for (int nt = 0; nt < 10; nt++) {
            int cb = wn * 80 + nt * 8 + 2 * tg;
            #pragma unroll
            for (int q = 0; q < 4; q++) {
                int grr = r0 + (q >> 1) * 8;
                int c   = cb + (q & 1);
                if (grr < M && c < Nc) {
                    float v = acc[mt][nt][q] + (bias ? bias[c] : 0.0f);
                    if (act == 1) v = fmaxf(v, 0.0f);
                    else if (act == 2) v = tanhf(v);
                    C[(size_t)grr * LD + c] = v;
                }
            }
        }
    }
}

// ----------------------- dual-set sparse propagation -----------------------
// One block (320 threads) per node. Threads 0..159 gather feature-set A,
// threads 160..319 feature-set B, sharing the SAME edge walk (metadata loads
// are warp-uniform broadcasts; gathers stay fully coalesced per half-block).
__global__ __launch_bounds__(320)
void k_prop2(int inA, int inB, int outA, int outB)
{
    int n = blockIdx.x;
    int t = threadIdx.x;
    int half = (t >= LD);
    int d = half ? (t - LD) : t;
    if (d >= HID) return;

    const float* __restrict__ in = BUF(half ? inB : inA);
    float* outb = BUF(half ? outB : outA);

    int b = g_rowptr[n], e = g_rowptr[n + 1];
    float p = 0.0f;
    int i = b;
    for (; i + 3 < e; i += 4) {
        int   s0 = g_csrc[i],   s1 = g_csrc[i+1], s2 = g_csrc[i+2], s3 = g_csrc[i+3];
        float w0 = g_cw[i],     w1 = g_cw[i+1],   w2 = g_cw[i+2],   w3 = g_cw[i+3];
        p = fmaf(w0, in[(size_t)s0 * LD + d], p);
        p = fmaf(w1, in[(size_t)s1 * LD + d], p);
        p = fmaf(w2, in[(size_t)s2 * LD + d], p);
        p = fmaf(w3, in[(size_t)s3 * LD + d], p);
    }
    for (; i < e; i++)
        p = fmaf(g_cw[i], in[(size_t)g_csrc[i] * LD + d], p);

    outb[(size_t)n * LD + d] = p;
}

// ------------------------- filter-bias projection --------------------------
__global__ void k_hb(const float* __restrict__ b_filt,
                     const float* __restrict__ Wf,
                     const float* __restrict__ bf)
{
    int idx = blockIdx.x * blockDim.x + threadIdx.x;
    if (idx >= FN * HID) return;
    int f = idx / HID, d = idx % HID;
    float a = bf[d];
    for (int e = 0; e < HID; e++)
        a = fmaf(b_filt[f * HID + e], Wf[e * HID + d], a);
    g_hb[f * LD + d] = a;
}

// ------------------------------ final fusion -------------------------------
__global__ void k_final(const float* __restrict__ theta,
                        const float* __restrict__ b_filt,
                        const float* __restrict__ Wc,
                        const float* __restrict__ bc,
                        float* __restrict__ out)
{
    int warp = (blockIdx.x * blockDim.x + threadIdx.x) >> 5;
    int lane = threadIdx.x & 31;
    if (warp >= NN) return;

    float cf[FN][3];
    float uf[FN], vf[FN], wf[FN];
    #pragma unroll
    for (int f = 0; f < FN; f++) {
        #pragma unroll
        for (int k = 0; k < 3; k++)
            cf[f][k] = fmaxf(theta[f * 3 + k], 0.0f);
        uf[f] = 0.25f * cf[f][0] + 0.5f * cf[f][1] + 0.25f * cf[f][2];
        vf[f] = 0.5f  * cf[f][0] - 0.5f * cf[f][2];
        wf[f] = 0.25f * cf[f][0] - 0.5f * cf[f][1] + 0.25f * cf[f][2];
    }

    const float* H  = BUF(S_H)  + (size_t)warp * LD;
    const float* P  = BUF(S_P)  + (size_t)warp * LD;
    const float* Q  = BUF(S_Q)  + (size_t)warp * LD;
    const float* HF = BUF(S_HF) + (size_t)warp * LD;
    const float* PF = BUF(S_PF) + (size_t)warp * LD;
    const float* QF = BUF(S_QF) + (size_t)warp * LD;
    const float* XP = BUF(S_XP) + (size_t)warp * LD;

    float lg[FN] = {0.f, 0.f, 0.f, 0.f};
    for (int d = lane; d < HID; d += 32) {
        float hf = HF[d], pf = PF[d], qf = QF[d];
        float xv = XP[d];
        #pragma unroll
        for (int f = 0; f < FN; f++) {
            float hp = tanhf(fmaf(uf[f], hf,
                             fmaf(vf[f], pf,
                             fmaf(wf[f], qf, g_hb[f * LD + d]))));
            lg[f] = fmaf(hp, xv, lg[f]);
        }
    }
    #pragma unroll
    for (int o = 16; o > 0; o >>= 1)
        #pragma unroll
        for (int f = 0; f < FN; f++)
            lg[f] += __shfl_xor_sync(0xffffffffu, lg[f], o);

    float m = fmaxf(fmaxf(lg[0], lg[1]), fmaxf(lg[2], lg[3]));
    float ex[FN], s = 0.0f;
    #pragma unroll
    for (int f = 0; f < FN; f++) { ex[f] = expf(lg[f] - m); s += ex[f]; }
    float inv = 1.0f / s;
    float sc[FN];
    #pragma unroll
    for (int f = 0; f < FN; f++) sc[f] = ex[f] * inv;

    float cu = 0.f, cv = 0.f, cw = 0.f;
    #pragma unroll
    for (int f = 0; f < FN; f++) {
        cu = fmaf(sc[f], uf[f], cu);
        cv = fmaf(sc[f], vf[f], cv);
        cw = fmaf(sc[f], wf[f], cw);
    }

    float o0 = 0.f, o1 = 0.f;
    for (int d = lane; d < HID; d += 32) {
        float r = cu * H[d] + cv * P[d] + cw * Q[d];
        #pragma unroll
        for (int f = 0; f < FN; f++)
            r = fmaf(sc[f], b_filt[f * HID + d], r);
        o0 = fmaf(r, Wc[2 * d + 0], o0);
        o1 = fmaf(r, Wc[2 * d + 1], o1);
    }
    #pragma unroll
    for (int o = 16; o > 0; o >>= 1) {
        o0 += __shfl_xor_sync(0xffffffffu, o0, o);
        o1 += __shfl_xor_sync(0xffffffffu, o1, o);
    }
    if (lane == 0) {
        out[warp * 2 + 0] = o0 + bc[0];
        out[warp * 2 + 1] = o1 + bc[1];
    }
}

// ------------------------------- launch ------------------------------------
extern "C" void kernel_launch(void* const* d_in, const int* in_sizes, int n_in,
                              void* d_out, int out_size)
{
    const float* x      = (const float*)d_in[0];
    const void*  ei     = d_in[1];
    const float* W1     = (const float*)d_in[2];
    const float* b1     = (const float*)d_in[3];
    const float* W2     = (const float*)d_in[4];
    const float* b2     = (const float*)d_in[5];
    const float* theta  = (const float*)d_in[6];
    const float* b_filt = (const float*)d_in[7];
    const float* Wf     = (const float*)d_in[8];
    const float* bf     = (const float*)d_in[9];
    const float* Wx     = (const float*)d_in[10];
    const float* bx     = (const float*)d_in[11];
    const float* Wc     = (const float*)d_in[12];
    const float* bc     = (const float*)d_in[13];
    float*       out    = (float*)d_out;

    static cudaStream_t s1 = nullptr;
    static cudaEvent_t evFork = nullptr, evCSR = nullptr, evH = nullptr,
                       evXP = nullptr;
    if (!s1) {
        cudaStreamCreateWithFlags(&s1, cudaStreamNonBlocking);
        cudaEventCreateWithFlags(&evFork, cudaEventDisableTiming);
        cudaEventCreateWithFlags(&evCSR,  cudaEventDisableTiming);
        cudaEventCreateWithFlags(&evH,    cudaEventDisableTiming);
        cudaEventCreateWithFlags(&evXP,   cudaEventDisableTiming);
    }
    cudaStream_t s0 = 0;

    const int TB = 256;
    dim3 gB2((NN + TB - 1) / TB);
    dim3 gE ((EE + TB - 1) / TB);
    dim3 gD ((DET_N + TB - 1) / TB);
    dim3 gemmGrid((NN + 127) / 128);

    cudaEventRecord(evFork, s0);
    cudaStreamWaitEvent(s1, evFork, 0);

    // ---- side stream: hb + CSR build (overlaps the MLP GEMMs) ----
    k_hb   <<<(FN * HID + TB - 1) / TB, TB, 0, s1>>>(b_filt, Wf, bf);
    k_zero <<<gB2, TB, 0, s1>>>();
    k_det  <<<gD,  TB, 0, s1>>>((const int*)ei);
    k_count<<<gE,  TB, 0, s1>>>(ei);
    k_scan1<<<NB_SCAN, 512, 0, s1>>>();
    k_scan2<<<1, 1, 0, s1>>>();
    k_scan3<<<NB_SCAN, 512, 0, s1>>>();
    k_fill <<<gE,  TB, 0, s1>>>(ei);
    cudaEventRecord(evCSR, s1);

    // ---- main stream: input MLP, then HF = h @ Wf (needed by props) ----
    k_gemm_tf32<<<gemmGrid, TB, 0, s0>>>(x,       -1,  INF, W1, b1, S_T,  NN, INF, HID, 1);
    k_gemm_tf32<<<gemmGrid, TB, 0, s0>>>(nullptr, S_T, LD,  W2, b2, S_H,  NN, HID, HID, 0);
    cudaEventRecord(evH, s0);
    k_gemm_tf32<<<gemmGrid, TB, 0, s0>>>(nullptr, S_H, LD,  Wf,
                                         (const float*)nullptr, S_HF, NN, HID, HID, 0);

    // ---- side stream: XP = tanh(h@Wx+bx) (overlaps HF gemm + props) ----
    cudaStreamWaitEvent(s1, evH, 0);
    k_gemm_tf32<<<gemmGrid, TB, 0, s1>>>(nullptr, S_H, LD, Wx, bx, S_XP, NN, HID, HID, 2);
    cudaEventRecord(evXP, s1);

    // ---- main stream: dual props: [p,PF] = A_hat [h,HF]; [q,QF] = A_hat [p,PF]
    cudaStreamWaitEvent(s0, evCSR, 0);
    k_prop2<<<NN, 320, 0, s0>>>(S_H, S_HF, S_P, S_PF);
    k_prop2<<<NN, 320, 0, s0>>>(S_P, S_PF, S_Q, S_QF);

    // ---- join + fusion + head ----
    cudaStreamWaitEvent(s0, evXP, 0);
    k_final<<<(NN * 32 + TB - 1) / TB, TB, 0, s0>>>(theta, b_filt, Wc, bc, out);
}

// round 11
// speedup vs baseline: 1.5507x; 1.5507x over previous
#include <cuda_runtime.h>
#include <math.h>
#include <stdint.h>

// ---------------------------------------------------------------------------
// AMNet: GCN-normalized Bernstein-filter GNN.
// Basis identity: with p = A_hat h, q = A_hat p,
//   B0 = 0.25(h + 2p + q), B1 = 0.5(h - q), B2 = 0.25(h - 2p + q)
#define NN   100000
#define EE   1600000
#define INF  166
#define HID  156
#define LD   160
#define FN   4
#define NB_SCAN 196
#define DET_N 65536

#define S_H  0
#define S_P  1
#define S_Q  2
#define S_HF 3
#define S_PF 4
#define S_QF 5
#define S_XP 6
#define S_T  7

__device__ float g_buf[(size_t)8 * NN * LD];
__device__ float g_hb[FN * LD];
__device__ float g_dinv[NN];
__device__ int   g_deg[NN];
__device__ int   g_cur[NN];
__device__ int   g_rowptr[NN + 1];
__device__ int   g_csrc[EE];
__device__ float g_cw[EE];
__device__ int   g_bsum[NB_SCAN];
__device__ int   g_odd_or;   // 0 => edge_index int64; nonzero => int32

__device__ __forceinline__ float* BUF(int i)
{
    return g_buf + (size_t)i * (NN * LD);
}

__device__ __forceinline__ int clampN(int v)
{
    return ((unsigned)v >= (unsigned)NN) ? 0 : v;
}

__device__ __forceinline__ int edge_at(const void* ei, long long j)
{
    if (g_odd_or == 0) return clampN((int)((const long long*)ei)[j]);
    return clampN(((const int*)ei)[j]);
}

// ---------------------------- CSR construction -----------------------------
__global__ void k_zero()
{
    int i = blockIdx.x * blockDim.x + threadIdx.x;
    if (i == 0) g_odd_or = 0;
    if (i < NN) { g_deg[i] = 0; g_cur[i] = 0; }
}

__global__ void k_det(const int* __restrict__ w)
{
    int i = blockIdx.x * blockDim.x + threadIdx.x;
    if (i < DET_N) {
        if (w[2 * i + 1] != 0) atomicOr(&g_odd_or, 1);
    }
}

__global__ void k_count(const void* ei)
{
    int e = blockIdx.x * blockDim.x + threadIdx.x;
    if (e < EE) atomicAdd(&g_deg[edge_at(ei, (long long)EE + e)], 1);
}

__global__ void k_scan1()
{
    __shared__ int s[512];
    int tid = threadIdx.x;
    int i = blockIdx.x * 512 + tid;
    int v = (i < NN) ? g_deg[i] : 0;
    if (i < NN) g_dinv[i] = rsqrtf(fmaxf((float)v, 1.0f));
    s[tid] = v;
    __syncthreads();
    for (int off = 1; off < 512; off <<= 1) {
        int t = (tid >= off) ? s[tid - off] : 0;
        __syncthreads();
        s[tid] += t;
        __syncthreads();
    }
    if (i < NN) g_rowptr[i] = s[tid] - v;
    if (tid == 511) g_bsum[blockIdx.x] = s[511];
}

__global__ void k_scan2()
{
    int acc = 0;
    for (int i = 0; i < NB_SCAN; i++) {
        int t = g_bsum[i];
        g_bsum[i] = acc;
        acc += t;
    }
    g_rowptr[NN] = EE;
}

__global__ void k_scan3()
{
    int i = blockIdx.x * 512 + threadIdx.x;
    if (i < NN) g_rowptr[i] += g_bsum[blockIdx.x];
}

__global__ void k_fill(const void* ei)
{
    int e = blockIdx.x * blockDim.x + threadIdx.x;
    if (e < EE) {
        int s = edge_at(ei, e);
        int d = edge_at(ei, (long long)EE + e);
        int pos = atomicAdd(&g_cur[d], 1);
        int idx = g_rowptr[d] + pos;
        g_csrc[idx] = s;
        g_cw[idx]   = g_dinv[s] * g_dinv[d];
    }
}

// ------------------------- tf32 tensor-core GEMM ---------------------------
__device__ __forceinline__ uint32_t f2tf32(float f)
{
    uint32_t r;
    asm("cvt.rna.tf32.f32 %0, %1;" : "=r"(r) : "f"(f));
    return r;
}

__device__ __forceinline__ void mma8(float* c, const uint32_t* a,
                                     uint32_t b0, uint32_t b1)
{
    asm volatile(
        "mma.sync.aligned.m16n8k8.row.col.f32.tf32.tf32.f32 "
        "{%0,%1,%2,%3}, {%4,%5,%6,%7}, {%8,%9}, {%0,%1,%2,%3};"
        : "+f"(c[0]), "+f"(c[1]), "+f"(c[2]), "+f"(c[3])
        : "r"(a[0]), "r"(a[1]), "r"(a[2]), "r"(a[3]), "r"(b0), "r"(b1));
}

// C[M x Nc] = act(A[M x Kc] @ W[Kc x Nc] + bias). Block tile 128x160, BK=32.
// Register-prefetch pipelined.
__global__ __launch_bounds__(256)
void k_gemm_tf32(const float* __restrict__ Aext, int Asel, int lda,
                 const float* __restrict__ W,
                 const float* __restrict__ bias,
                 int Csel, int M, int Kc, int Nc, int act)
{
    __shared__ uint32_t As[128][36];
    __shared__ uint32_t Bs[32][168];

    const float* A = (Asel >= 0) ? BUF(Asel) : Aext;
    float*       C = BUF(Csel);

    int t = threadIdx.x;
    int lane = t & 31, warp = t >> 5;
    int wm = warp & 3, wn = warp >> 2;
    int g = lane >> 2, tg = lane & 3;
    int rowbase = blockIdx.x * 128;

    int ar  = t >> 1;
    int ac0 = (t & 1) * 16;
    int gr  = rowbase + ar;
    bool rok = gr < M;
    const float* Arow = A + (size_t)gr * lda + ac0;

    float ra[16], rb[20];

    #pragma unroll
    for (int i = 0; i < 16; i++) {
        int gk = ac0 + i;
        ra[i] = (rok && gk < Kc) ? Arow[i] : 0.0f;
    }
    #pragma unroll
    for (int i = 0; i < 20; i++) {
        int idx = t + i * 256;
        int r = idx / 160, c = idx - r * 160;
        rb[i] = (r < Kc && c < Nc) ? W[r * Nc + c] : 0.0f;
    }

    float acc[2][10][4];
    #pragma unroll
    for (int mt = 0; mt < 2; mt++)
        #pragma unroll
        for (int nt = 0; nt < 10; nt++)
            #pragma unroll
            for (int q = 0; q < 4; q++) acc[mt][nt][q] = 0.0f;

    for (int k0 = 0; k0 < Kc; k0 += 32) {
        #pragma unroll
        for (int i = 0; i < 16; i++)
            As[ar][ac0 + i] = f2tf32(ra[i]);
        #pragma unroll
        for (int i = 0; i < 20; i++) {
            int idx = t + i * 256;
            int r = idx / 160, c = idx - r * 160;
            Bs[r][c] = f2tf32(rb[i]);
        }
        __syncthreads();

        int kn = k0 + 32;
        if (kn < Kc) {
            const float* An = Arow + kn;
            #pragma unroll
            for (int i = 0; i < 16; i++) {
                int gk = kn + ac0 + i;
                ra[i] = (rok && gk < Kc) ? An[i] : 0.0f;
            }
            #pragma unroll
            for (int i = 0; i < 20; i++) {
                int idx = t + i * 256;
                int r = idx / 160, c = idx - r * 160;
                int gk = kn + r;
                rb[i] = (gk < Kc && c < Nc) ? W[gk * Nc + c] : 0.0f;
            }
        }

        #pragma unroll
        for (int kk = 0; kk < 32; kk += 8) {
            uint32_t a[2][4];
            #pragma unroll
            for (int mt = 0; mt < 2; mt++) {
                int mr = wm * 32 + mt * 16 + g;
                a[mt][0] = As[mr][kk + tg];
                a[mt][1] = As[mr + 8][kk + tg];
                a[mt][2] = As[mr][kk + tg + 4];
                a[mt][3] = As[mr + 8][kk + tg + 4];
            }
            #pragma unroll
            for (int nt = 0; nt < 10; nt++) {
                int nb = wn * 80 + nt * 8 + g;
                uint32_t b0 = Bs[kk + tg][nb];
                uint32_t b1 = Bs[kk + tg + 4][nb];
                mma8(acc[0][nt], a[0], b0, b1);
                mma8(acc[1][nt], a[1], b0, b1);
            }
        }
        __syncthreads();
    }

    #pragma unroll
    for (int mt = 0; mt < 2; mt++) {
        int r0 = rowbase + wm * 32 + mt * 16 + g;
        #pragma unroll
        for (int nt = 0; nt < 10; nt++) {
            int cb = wn * 80 + nt * 8 + 2 * tg;
            #pragma unroll
            for (int q = 0; q < 4; q++) {
                int grr = r0 + (q >> 1) * 8;
                int c   = cb + (q & 1);
                if (grr < M && c < Nc) {
                    float v = acc[mt][nt][q] + (bias ? bias[c] : 0.0f);
                    if (act == 1) v = fmaxf(v, 0.0f);
                    else if (act == 2) v = tanhf(v);
                    C[(size_t)grr * LD + c] = v;
                }
            }
        }
    }
}

// -------------------------- sparse propagation -----------------------------
// One block (160 threads) per node; thread d owns feature dim d. (R5 version)
__global__ void k_prop(int insel, int outsel)
{
    const float* __restrict__ in = BUF(insel);
    float* outb = BUF(outsel);

    int n = blockIdx.x;
    int d = threadIdx.x;
    if (d >= HID) return;

    int b = g_rowptr[n], e = g_rowptr[n + 1];
    float p = 0.0f;
    int i = b;
    for (; i + 3 < e; i += 4) {
        int   s0 = g_csrc[i],   s1 = g_csrc[i+1], s2 = g_csrc[i+2], s3 = g_csrc[i+3];
        float w0 = g_cw[i],     w1 = g_cw[i+1],   w2 = g_cw[i+2],   w3 = g_cw[i+3];
        p = fmaf(w0, in[(size_t)s0 * LD + d], p);
        p = fmaf(w1, in[(size_t)s1 * LD + d], p);
        p = fmaf(w2, in[(size_t)s2 * LD + d], p);
        p = fmaf(w3, in[(size_t)s3 * LD + d], p);
    }
    for (; i < e; i++)
        p = fmaf(g_cw[i], in[(size_t)g_csrc[i] * LD + d], p);

    outb[(size_t)n * LD + d] = p;
}

// ------------------------- filter-bias projection --------------------------
__global__ void k_hb(const float* __restrict__ b_filt,
                     const float* __restrict__ Wf,
                     const float* __restrict__ bf)
{
    int idx = blockIdx.x * blockDim.x + threadIdx.x;
    if (idx >= FN * HID) return;
    int f = idx / HID, d = idx % HID;
    float a = bf[d];
    for (int e = 0; e < HID; e++)
        a = fmaf(b_filt[f * HID + e], Wf[e * HID + d], a);
    g_hb[f * LD + d] = a;
}

// ------------------------------ final fusion -------------------------------
__global__ void k_final(const float* __restrict__ theta,
                        const float* __restrict__ b_filt,
                        const float* __restrict__ Wc,
                        const float* __restrict__ bc,
                        float* __restrict__ out)
{
    int warp = (blockIdx.x * blockDim.x + threadIdx.x) >> 5;
    int lane = threadIdx.x & 31;
    if (warp >= NN) return;

    float cf[FN][3];
    float uf[FN], vf[FN], wf[FN];
    #pragma unroll
    for (int f = 0; f < FN; f++) {
        #pragma unroll
        for (int k = 0; k < 3; k++)
            cf[f][k] = fmaxf(theta[f * 3 + k], 0.0f);
        uf[f] = 0.25f * cf[f][0] + 0.5f * cf[f][1] + 0.25f * cf[f][2];
        vf[f] = 0.5f  * cf[f][0] - 0.5f * cf[f][2];
        wf[f] = 0.25f * cf[f][0] - 0.5f * cf[f][1] + 0.25f * cf[f][2];
    }

    const float* H  = BUF(S_H)  + (size_t)warp * LD;
    const float* P  = BUF(S_P)  + (size_t)warp * LD;
    const float* Q  = BUF(S_Q)  + (size_t)warp * LD;
    const float* HF = BUF(S_HF) + (size_t)warp * LD;
    const float* PF = BUF(S_PF) + (size_t)warp * LD;
    const float* QF = BUF(S_QF) + (size_t)warp * LD;
    const float* XP = BUF(S_XP) + (size_t)warp * LD;

    float lg[FN] = {0.f, 0.f, 0.f, 0.f};
    for (int d = lane; d < HID; d += 32) {
        float hf = HF[d], pf = PF[d], qf = QF[d];
        float xv = XP[d];
        #pragma unroll
        for (int f = 0; f < FN; f++) {
            float hp = tanhf(fmaf(uf[f], hf,
                             fmaf(vf[f], pf,
                             fmaf(wf[f], qf, g_hb[f * LD + d]))));
            lg[f] = fmaf(hp, xv, lg[f]);
        }
    }
    #pragma unroll
    for (int o = 16; o > 0; o >>= 1)
        #pragma unroll
        for (int f = 0; f < FN; f++)
            lg[f] += __shfl_xor_sync(0xffffffffu, lg[f], o);

    float m = fmaxf(fmaxf(lg[0], lg[1]), fmaxf(lg[2], lg[3]));
    float ex[FN], s = 0.0f;
    #pragma unroll
    for (int f = 0; f < FN; f++) { ex[f] = expf(lg[f] - m); s += ex[f]; }
    float inv = 1.0f / s;
    float sc[FN];
    #pragma unroll
    for (int f = 0; f < FN; f++) sc[f] = ex[f] * inv;

    float cu = 0.f, cv = 0.f, cw = 0.f;
    #pragma unroll
    for (int f = 0; f < FN; f++) {
        cu = fmaf(sc[f], uf[f], cu);
        cv = fmaf(sc[f], vf[f], cv);
        cw = fmaf(sc[f], wf[f], cw);
    }

    float o0 = 0.f, o1 = 0.f;
    for (int d = lane; d < HID; d += 32) {
        float r = cu * H[d] + cv * P[d] + cw * Q[d];
        #pragma unroll
        for (int f = 0; f < FN; f++)
            r = fmaf(sc[f], b_filt[f * HID + d], r);
        o0 = fmaf(r, Wc[2 * d + 0], o0);
        o1 = fmaf(r, Wc[2 * d + 1], o1);
    }
    #pragma unroll
    for (int o = 16; o > 0; o >>= 1) {
        o0 += __shfl_xor_sync(0xffffffffu, o0, o);
        o1 += __shfl_xor_sync(0xffffffffu, o1, o);
    }
    if (lane == 0) {
        out[warp * 2 + 0] = o0 + bc[0];
        out[warp * 2 + 1] = o1 + bc[1];
    }
}

// ------------------------------- launch ------------------------------------
extern "C" void kernel_launch(void* const* d_in, const int* in_sizes, int n_in,
                              void* d_out, int out_size)
{
    const float* x      = (const float*)d_in[0];
    const void*  ei     = d_in[1];
    const float* W1     = (const float*)d_in[2];
    const float* b1     = (const float*)d_in[3];
    const float* W2     = (const float*)d_in[4];
    const float* b2     = (const float*)d_in[5];
    const float* theta  = (const float*)d_in[6];
    const float* b_filt = (const float*)d_in[7];
    const float* Wf     = (const float*)d_in[8];
    const float* bf     = (const float*)d_in[9];
    const float* Wx     = (const float*)d_in[10];
    const float* bx     = (const float*)d_in[11];
    const float* Wc     = (const float*)d_in[12];
    const float* bc     = (const float*)d_in[13];
    float*       out    = (float*)d_out;

    static cudaStream_t s1 = nullptr;
    static cudaEvent_t evFork = nullptr, evCSR = nullptr, evH = nullptr,
                       evXP = nullptr;
    if (!s1) {
        cudaStreamCreateWithFlags(&s1, cudaStreamNonBlocking);
        cudaEventCreateWithFlags(&evFork, cudaEventDisableTiming);
        cudaEventCreateWithFlags(&evCSR,  cudaEventDisableTiming);
        cudaEventCreateWithFlags(&evH,    cudaEventDisableTiming);
        cudaEventCreateWithFlags(&evXP,   cudaEventDisableTiming);
    }
    cudaStream_t s0 = 0;

    const int TB = 256;
    dim3 gB2((NN + TB - 1) / TB);
    dim3 gE ((EE + TB - 1) / TB);
    dim3 gD ((DET_N + TB - 1) / TB);
    dim3 gemmGrid ((NN + 127) / 128);
    dim3 gemmGrid3((3 * NN + 127) / 128);

    cudaEventRecord(evFork, s0);
    cudaStreamWaitEvent(s1, evFork, 0);

    // ---- interleaved issue: the 4th kernel launched is g1 (the GEMM), so
    // the profiler's fixed sampling slot lands on it next round. ----
    k_hb   <<<(FN * HID + TB - 1) / TB, TB, 0, s1>>>(b_filt, Wf, bf);   // 1
    k_zero <<<gB2, TB, 0, s1>>>();                                       // 2
    k_det  <<<gD,  TB, 0, s1>>>((const int*)ei);                         // 3

    // ---- main stream: input MLP g1 (PROFILED SLOT) ----
    k_gemm_tf32<<<gemmGrid, TB, 0, s0>>>(x, -1, INF, W1, b1, S_T,        // 4
                                         NN, INF, HID, 1);

    // ---- side stream: rest of CSR build (overlaps the MLP GEMMs) ----
    k_count<<<gE,  TB, 0, s1>>>(ei);                                     // 5
    k_scan1<<<NB_SCAN, 512, 0, s1>>>();                                  // 6
    k_scan2<<<1, 1, 0, s1>>>();                                          // 7
    k_scan3<<<NB_SCAN, 512, 0, s1>>>();                                  // 8
    k_fill <<<gE,  TB, 0, s1>>>(ei);                                     // 9
    cudaEventRecord(evCSR, s1);

    // ---- main stream: g2 ----
    k_gemm_tf32<<<gemmGrid, TB, 0, s0>>>(nullptr, S_T, LD, W2, b2, S_H,  // 10
                                         NN, HID, HID, 0);
    cudaEventRecord(evH, s0);

    // ---- side stream: xp = tanh(h@Wx+bx) (overlaps the props) ----
    cudaStreamWaitEvent(s1, evH, 0);
    k_gemm_tf32<<<gemmGrid, TB, 0, s1>>>(nullptr, S_H, LD, Wx, bx, S_XP, // 11
                                         NN, HID, HID, 2);
    cudaEventRecord(evXP, s1);

    // ---- main stream: p = A_hat h ; q = A_hat p ----
    cudaStreamWaitEvent(s0, evCSR, 0);
    k_prop<<<NN, LD, 0, s0>>>(S_H, S_P);                                 // 12
    k_prop<<<NN, LD, 0, s0>>>(S_P, S_Q);                                 // 13

    // ---- [Hf;Pf;Qf] = [h;p;q] @ Wf (batched, M=3N) ----
    k_gemm_tf32<<<gemmGrid3, TB, 0, s0>>>(nullptr, S_H, LD, Wf,          // 14
                                          (const float*)nullptr,
                                          S_HF, 3 * NN, HID, HID, 0);

    // ---- join + fusion + head ----
    cudaStreamWaitEvent(s0, evXP, 0);
    k_final<<<(NN * 32 + TB - 1) / TB, TB, 0, s0>>>(theta, b_filt,       // 15
                                                    Wc, bc, out);
}

// round 12
// speedup vs baseline: 1.7865x; 1.1521x over previous
#include <cuda_runtime.h>
#include <math.h>
#include <stdint.h>

// ---------------------------------------------------------------------------
// AMNet: GCN-normalized Bernstein-filter GNN.
// Basis identity: with p = A_hat h, q = A_hat p,
//   B0 = 0.25(h + 2p + q), B1 = 0.5(h - q), B2 = 0.25(h - 2p + q)
#define NN   100000
#define EE   1600000
#define INF  166
#define HID  156
#define LD   160
#define FN   4
#define NB_SCAN 196
#define DET_N 65536

#define S_H  0
#define S_P  1
#define S_Q  2
#define S_HF 3
#define S_PF 4
#define S_QF 5
#define S_XP 6
#define S_T  7

__device__ float g_buf[(size_t)8 * NN * LD];
__device__ float g_hb[FN * LD];
__device__ float g_dinv[NN];
__device__ int   g_deg[NN];
__device__ int   g_cur[NN];
__device__ int   g_rowptr[NN + 1];
__device__ int   g_csrc[EE];
__device__ float g_cw[EE];
__device__ int   g_bsum[NB_SCAN];
__device__ int   g_odd_or;   // 0 => edge_index int64; nonzero => int32

__device__ __forceinline__ float* BUF(int i)
{
    return g_buf + (size_t)i * (NN * LD);
}

__device__ __forceinline__ int clampN(int v)
{
    return ((unsigned)v >= (unsigned)NN) ? 0 : v;
}

__device__ __forceinline__ int edge_at(const void* ei, long long j)
{
    if (g_odd_or == 0) return clampN((int)((const long long*)ei)[j]);
    return clampN(((const int*)ei)[j]);
}

// ---------------------------- CSR construction -----------------------------
__global__ void k_zero()
{
    int i = blockIdx.x * blockDim.x + threadIdx.x;
    if (i == 0) g_odd_or = 0;
    if (i < NN) { g_deg[i] = 0; g_cur[i] = 0; }
}

__global__ void k_det(const int* __restrict__ w)
{
    int i = blockIdx.x * blockDim.x + threadIdx.x;
    if (i < DET_N) {
        if (w[2 * i + 1] != 0) atomicOr(&g_odd_or, 1);
    }
}

__global__ void k_count(const void* ei)
{
    int e = blockIdx.x * blockDim.x + threadIdx.x;
    if (e < EE) atomicAdd(&g_deg[edge_at(ei, (long long)EE + e)], 1);
}

__global__ void k_scan1()
{
    __shared__ int s[512];
    int tid = threadIdx.x;
    int i = blockIdx.x * 512 + tid;
    int v = (i < NN) ? g_deg[i] : 0;
    if (i < NN) g_dinv[i] = rsqrtf(fmaxf((float)v, 1.0f));
    s[tid] = v;
    __syncthreads();
    for (int off = 1; off < 512; off <<= 1) {
        int t = (tid >= off) ? s[tid - off] : 0;
        __syncthreads();
        s[tid] += t;
        __syncthreads();
    }
    if (i < NN) g_rowptr[i] = s[tid] - v;
    if (tid == 511) g_bsum[blockIdx.x] = s[511];
}

__global__ void k_scan2()
{
    int acc = 0;
    for (int i = 0; i < NB_SCAN; i++) {
        int t = g_bsum[i];
        g_bsum[i] = acc;
        acc += t;
    }
    g_rowptr[NN] = EE;
}

__global__ void k_scan3()
{
    int i = blockIdx.x * 512 + threadIdx.x;
    if (i < NN) g_rowptr[i] += g_bsum[blockIdx.x];
}

__global__ void k_fill(const void* ei)
{
    int e = blockIdx.x * blockDim.x + threadIdx.x;
    if (e < EE) {
        int s = edge_at(ei, e);
        int d = edge_at(ei, (long long)EE + e);
        int pos = atomicAdd(&g_cur[d], 1);
        int idx = g_rowptr[d] + pos;
        g_csrc[idx] = s;
        g_cw[idx]   = g_dinv[s] * g_dinv[d];
    }
}

// ------------------------- tf32 tensor-core GEMM ---------------------------
__device__ __forceinline__ uint32_t f2tf32(float f)
{
    uint32_t r;
    asm("cvt.rna.tf32.f32 %0, %1;" : "=r"(r) : "f"(f));
    return r;
}

__device__ __forceinline__ void mma8(float* c, const uint32_t* a,
                                     uint32_t b0, uint32_t b1)
{
    asm volatile(
        "mma.sync.aligned.m16n8k8.row.col.f32.tf32.tf32.f32 "
        "{%0,%1,%2,%3}, {%4,%5,%6,%7}, {%8,%9}, {%0,%1,%2,%3};"
        : "+f"(c[0]), "+f"(c[1]), "+f"(c[2]), "+f"(c[3])
        : "r"(a[0]), "r"(a[1]), "r"(a[2]), "r"(a[3]), "r"(b0), "r"(b1));
}

// C[M x Nc] = act(A[M x Kc] @ W[Kc x Nc] + bias). Block tile 128x160, BK=16,
// register-prefetch pipelined, 2 CTAs/SM (cross-CTA latency hiding).
__global__ __launch_bounds__(256, 2)
void k_gemm_tf32(const float* __restrict__ Aext, int Asel, int lda,
                 const float* __restrict__ W,
                 const float* __restrict__ bias,
                 int Csel, int M, int Kc, int Nc, int act)
{
    __shared__ uint32_t As[128][20];   // pad 20: (20g+tg) mod 32 all-distinct
    __shared__ uint32_t Bs[16][168];   // pad 168: (8tg+g) mod 32 all-distinct

    const float* A = (Asel >= 0) ? BUF(Asel) : Aext;
    float*       C = BUF(Csel);

    int t = threadIdx.x;
    int lane = t & 31, warp = t >> 5;
    int wm = warp & 3, wn = warp >> 2;
    int g = lane >> 2, tg = lane & 3;
    int rowbase = blockIdx.x * 128;

    // A staging: row t>>1, 8 cols at (t&1)*8
    int ar  = t >> 1;
    int ac0 = (t & 1) * 8;
    int gr  = rowbase + ar;
    bool rok = gr < M;
    const float* Arow = A + (size_t)gr * lda + ac0;

    float ra[8], rb[10];

    #pragma unroll
    for (int i = 0; i < 8; i++) {
        int gk = ac0 + i;
        ra[i] = (rok && gk < Kc) ? Arow[i] : 0.0f;
    }
    #pragma unroll
    for (int i = 0; i < 10; i++) {
        int idx = t + i * 256;
        int r = idx / 160, c = idx - r * 160;
        rb[i] = (r < Kc && c < Nc) ? W[r * Nc + c] : 0.0f;
    }

    float acc[2][10][4];
    #pragma unroll
    for (int mt = 0; mt < 2; mt++)
        #pragma unroll
        for (int nt = 0; nt < 10; nt++)
            #pragma unroll
            for (int q = 0; q < 4; q++) acc[mt][nt][q] = 0.0f;

    for (int k0 = 0; k0 < Kc; k0 += 16) {
        #pragma unroll
        for (int i = 0; i < 8; i++)
            As[ar][ac0 + i] = f2tf32(ra[i]);
        #pragma unroll
        for (int i = 0; i < 10; i++) {
            int idx = t + i * 256;
            int r = idx / 160, c = idx - r * 160;
            Bs[r][c] = f2tf32(rb[i]);
        }
        __syncthreads();

        int kn = k0 + 16;
        if (kn < Kc) {
            const float* An = Arow + kn;
            #pragma unroll
            for (int i = 0; i < 8; i++) {
                int gk = kn + ac0 + i;
                ra[i] = (rok && gk < Kc) ? An[i] : 0.0f;
            }
            #pragma unroll
            for (int i = 0; i < 10; i++) {
                int idx = t + i * 256;
                int r = idx / 160, c = idx - r * 160;
                int gk = kn + r;
                rb[i] = (gk < Kc && c < Nc) ? W[gk * Nc + c] : 0.0f;
            }
        }

        #pragma unroll
        for (int kk = 0; kk < 16; kk += 8) {
            uint32_t a[2][4];
            #pragma unroll
            for (int mt = 0; mt < 2; mt++) {
                int mr = wm * 32 + mt * 16 + g;
                a[mt][0] = As[mr][kk + tg];
                a[mt][1] = As[mr + 8][kk + tg];
                a[mt][2] = As[mr][kk + tg + 4];
                a[mt][3] = As[mr + 8][kk + tg + 4];
            }
            #pragma unroll
            for (int nt = 0; nt < 10; nt++) {
                int nb = wn * 80 + nt * 8 + g;
                uint32_t b0 = Bs[kk + tg][nb];
                uint32_t b1 = Bs[kk + tg + 4][nb];
                mma8(acc[0][nt], a[0], b0, b1);
                mma8(acc[1][nt], a[1], b0, b1);
            }
        }
        __syncthreads();
    }

    #pragma unroll
    for (int mt = 0; mt < 2; mt++) {
        int r0 = rowbase + wm * 32 + mt * 16 + g;
        #pragma unroll
        for (int nt = 0; nt < 10; nt++) {
            int cb = wn * 80 + nt * 8 + 2 * tg;
            #pragma unroll
            for (int q = 0; q < 4; q++) {
                int grr = r0 + (q >> 1) * 8;
                int c   = cb + (q & 1);
                if (grr < M && c < Nc) {
                    float v = acc[mt][nt][q] + (bias ? bias[c] : 0.0f);
                    if (act == 1) v = fmaxf(v, 0.0f);
                    else if (act == 2) v = tanhf(v);
                    C[(size_t)grr * LD + c] = v;
                }
            }
        }
    }
}

// -------------------------- sparse propagation -----------------------------
__global__ void k_prop(int insel, int outsel)
{
    const float* __restrict__ in = BUF(insel);
    float* outb = BUF(outsel);

    int n = blockIdx.x;
    int d = threadIdx.x;
    if (d >= HID) return;

    int b = g_rowptr[n], e = g_rowptr[n + 1];
    float p = 0.0f;
    int i = b;
    for (; i + 3 < e; i += 4) {
        int   s0 = g_csrc[i],   s1 = g_csrc[i+1], s2 = g_csrc[i+2], s3 = g_csrc[i+3];
        float w0 = g_cw[i],     w1 = g_cw[i+1],   w2 = g_cw[i+2],   w3 = g_cw[i+3];
        p = fmaf(w0, in[(size_t)s0 * LD + d], p);
        p = fmaf(w1, in[(size_t)s1 * LD + d], p);
        p = fmaf(w2, in[(size_t)s2 * LD + d], p);
        p = fmaf(w3, in[(size_t)s3 * LD + d], p);
    }
    for (; i < e; i++)
        p = fmaf(g_cw[i], in[(size_t)g_csrc[i] * LD + d], p);

    outb[(size_t)n * LD + d] = p;
}

// ------------------------- filter-bias projection --------------------------
__global__ void k_hb(const float* __restrict__ b_filt,
                     const float* __restrict__ Wf,
                     const float* __restrict__ bf)
{
    int idx = blockIdx.x * blockDim.x + threadIdx.x;
    if (idx >= FN * HID) return;
    int f = idx / HID, d = idx % HID;
    float a = bf[d];
    for (int e = 0; e < HID; e++)
        a = fmaf(b_filt[f * HID + e], Wf[e * HID + d], a);
    g_hb[f * LD + d] = a;
}

// ------------------------------ final fusion -------------------------------
__global__ void k_final(const float* __restrict__ theta,
                        const float* __restrict__ b_filt,
                        const float* __restrict__ Wc,
                        const float* __restrict__ bc,
                        float* __restrict__ out)
{
    int warp = (blockIdx.x * blockDim.x + threadIdx.x) >> 5;
    int lane = threadIdx.x & 31;
    if (warp >= NN) return;

    float cf[FN][3];
    float uf[FN], vf[FN], wf[FN];
    #pragma unroll
    for (int f = 0; f < FN; f++) {
        #pragma unroll
        for (int k = 0; k < 3; k++)
            cf[f][k] = fmaxf(theta[f * 3 + k], 0.0f);
        uf[f] = 0.25f * cf[f][0] + 0.5f * cf[f][1] + 0.25f * cf[f][2];
        vf[f] = 0.5f  * cf[f][0] - 0.5f * cf[f][2];
        wf[f] = 0.25f * cf[f][0] - 0.5f * cf[f][1] + 0.25f * cf[f][2];
    }

    const float* H  = BUF(S_H)  + (size_t)warp * LD;
    const float* P  = BUF(S_P)  + (size_t)warp * LD;
    const float* Q  = BUF(S_Q)  + (size_t)warp * LD;
    const float* HF = BUF(S_HF) + (size_t)warp * LD;
    const float* PF = BUF(S_PF) + (size_t)warp * LD;
    const float* QF = BUF(S_QF) + (size_t)warp * LD;
    const float* XP = BUF(S_XP) + (size_t)warp * LD;

    float lg[FN] = {0.f, 0.f, 0.f, 0.f};
    for (int d = lane; d < HID; d += 32) {
        float hf = HF[d], pf = PF[d], qf = QF[d];
        float xv = XP[d];
        #pragma unroll
        for (int f = 0; f < FN; f++) {
            float hp = tanhf(fmaf(uf[f], hf,
                             fmaf(vf[f], pf,
                             fmaf(wf[f], qf, g_hb[f * LD + d]))));
            lg[f] = fmaf(hp, xv, lg[f]);
        }
    }
    #pragma unroll
    for (int o = 16; o > 0; o >>= 1)
        #pragma unroll
        for (int f = 0; f < FN; f++)
            lg[f] += __shfl_xor_sync(0xffffffffu, lg[f], o);

    float m = fmaxf(fmaxf(lg[0], lg[1]), fmaxf(lg[2], lg[3]));
    float ex[FN], s = 0.0f;
    #pragma unroll
    for (int f = 0; f < FN; f++) { ex[f] = expf(lg[f] - m); s += ex[f]; }
    float inv = 1.0f / s;
    float sc[FN];
    #pragma unroll
    for (int f = 0; f < FN; f++) sc[f] = ex[f] * inv;

    float cu = 0.f, cv = 0.f, cw = 0.f;
    #pragma unroll
    for (int f = 0; f < FN; f++) {
        cu = fmaf(sc[f], uf[f], cu);
        cv = fmaf(sc[f], vf[f], cv);
        cw = fmaf(sc[f], wf[f], cw);
    }

    float o0 = 0.f, o1 = 0.f;
    for (int d = lane; d < HID; d += 32) {
        float r = cu * H[d] + cv * P[d] + cw * Q[d];
        #pragma unroll
        for (int f = 0; f < FN; f++)
            r = fmaf(sc[f], b_filt[f * HID + d], r);
        o0 = fmaf(r, Wc[2 * d + 0], o0);
        o1 = fmaf(r, Wc[2 * d + 1], o1);
    }
    #pragma unroll
    for (int o = 16; o > 0; o >>= 1) {
        o0 += __shfl_xor_sync(0xffffffffu, o0, o);
        o1 += __shfl_xor_sync(0xffffffffu, o1, o);
    }
    if (lane == 0) {
        out[warp * 2 + 0] = o0 + bc[0];
        out[warp * 2 + 1] = o1 + bc[1];
    }
}

// ------------------------------- launch ------------------------------------
extern "C" void kernel_launch(void* const* d_in, const int* in_sizes, int n_in,
                              void* d_out, int out_size)
{
    const float* x      = (const float*)d_in[0];
    const void*  ei     = d_in[1];
    const float* W1     = (const float*)d_in[2];
    const float* b1     = (const float*)d_in[3];
    const float* W2     = (const float*)d_in[4];
    const float* b2     = (const float*)d_in[5];
    const float* theta  = (const float*)d_in[6];
    const float* b_filt = (const float*)d_in[7];
    const float* Wf     = (const float*)d_in[8];
    const float* bf     = (const float*)d_in[9];
    const float* Wx     = (const float*)d_in[10];
    const float* bx     = (const float*)d_in[11];
    const float* Wc     = (const float*)d_in[12];
    const float* bc     = (const float*)d_in[13];
    float*       out    = (float*)d_out;

    static cudaStream_t s1 = nullptr;
    static cudaEvent_t evFork = nullptr, evCSR = nullptr, evH = nullptr,
                       evXP = nullptr;
    if (!s1) {
        cudaStreamCreateWithFlags(&s1, cudaStreamNonBlocking);
        cudaEventCreateWithFlags(&evFork, cudaEventDisableTiming);
        cudaEventCreateWithFlags(&evCSR,  cudaEventDisableTiming);
        cudaEventCreateWithFlags(&evH,    cudaEventDisableTiming);
        cudaEventCreateWithFlags(&evXP,   cudaEventDisableTiming);
    }
    cudaStream_t s0 = 0;

    const int TB = 256;
    dim3 gB2((NN + TB - 1) / TB);
    dim3 gE ((EE + TB - 1) / TB);
    dim3 gD ((DET_N + TB - 1) / TB);
    dim3 gemmGrid ((NN + 127) / 128);
    dim3 gemmGrid3((3 * NN + 127) / 128);

    cudaEventRecord(evFork, s0);
    cudaStreamWaitEvent(s1, evFork, 0);

    // ---- keep g1 as the 4th launched kernel (profiled slot) ----
    k_hb   <<<(FN * HID + TB - 1) / TB, TB, 0, s1>>>(b_filt, Wf, bf);   // 1
    k_zero <<<gB2, TB, 0, s1>>>();                                       // 2
    k_det  <<<gD,  TB, 0, s1>>>((const int*)ei);                         // 3

    // ---- main stream: input MLP g1 (PROFILED SLOT) ----
    k_gemm_tf32<<<gemmGrid, TB, 0, s0>>>(x, -1, INF, W1, b1, S_T,        // 4
                                         NN, INF, HID, 1);

    // ---- side stream: rest of CSR build (overlaps the MLP GEMMs) ----
    k_count<<<gE,  TB, 0, s1>>>(ei);                                     // 5
    k_scan1<<<NB_SCAN, 512, 0, s1>>>();                                  // 6
    k_scan2<<<1, 1, 0, s1>>>();                                          // 7
    k_scan3<<<NB_SCAN, 512, 0, s1>>>();                                  // 8
    k_fill <<<gE,  TB, 0, s1>>>(ei);                                     // 9
    cudaEventRecord(evCSR, s1);

    // ---- main stream: g2 ----
    k_gemm_tf32<<<gemmGrid, TB, 0, s0>>>(nullptr, S_T, LD, W2, b2, S_H,  // 10
                                         NN, HID, HID, 0);
    cudaEventRecord(evH, s0);

    // ---- side stream: xp = tanh(h@Wx+bx) (overlaps the props) ----
    cudaStreamWaitEvent(s1, evH, 0);
    k_gemm_tf32<<<gemmGrid, TB, 0, s1>>>(nullptr, S_H, LD, Wx, bx, S_XP, // 11
                                         NN, HID, HID, 2);
    cudaEventRecord(evXP, s1);

    // ---- main stream: p = A_hat h ; q = A_hat p ----
    cudaStreamWaitEvent(s0, evCSR, 0);
    k_prop<<<NN, LD, 0, s0>>>(S_H, S_P);                                 // 12
    k_prop<<<NN, LD, 0, s0>>>(S_P, S_Q);                                 // 13

    // ---- [Hf;Pf;Qf] = [h;p;q] @ Wf (batched, M=3N) ----
    k_gemm_tf32<<<gemmGrid3, TB, 0, s0>>>(nullptr, S_H, LD, Wf,          // 14
                                          (const float*)nullptr,
                                          S_HF, 3 * NN, HID, HID, 0);

    // ---- join + fusion + head ----
    cudaStreamWaitEvent(s0, evXP, 0);
    k_final<<<(NN * 32 + TB - 1) / TB, TB, 0, s0>>>(theta, b_filt,       // 15
                                                    Wc, bc, out);
}